// round 9
// baseline (speedup 1.0000x reference)
#include <cuda_runtime.h>
#include <cuda_fp16.h>
#include <math.h>
#include <stdint.h>

#define NN 100000

// ---------------- scratch ----------------
__device__ __align__(8) float2 g_nd[NN];     // (agg, deg) fused
__device__ float g_degmax;
__device__ float g_sum_s, g_sum_a, g_sum_ss, g_sum_aa, g_sum_sa;

// Compacted per-lane B fragments (only nonzero ones, 115 total):
//   L1: f 0..8 (nt, kt=0)
//   Hidden hl: f 9+33*hl + packed(nt, kt in mask, kt-ascending)
//   End: f 108..114 (nt0: 4 frags mask HM_LO, nt1: 3 frags mask HM_HI)
// frag f, lane l: .x = pack(B[k0][n], B[k0+1][n]), .y = pack(B[k0+8][n], B[k0+9][n])
//   with n = nt*8 + l/4, k0 = kt*16 + 2*(l%4)   (B[k][n] = W[n][k])
#define NFRAG 115
__device__ __align__(16) uint2 g_wfrag[NFRAG * 32];

// block-diagonal sparsity masks (bit kt set => fragment nonzero)
#define HM_LO  0b10111    // hidden, nt 0..3  (R block + bias)
#define HM_MID 0b11111    // hidden, nt 4
#define HM_HI  0b11100    // hidden, nt 5..8  (P block + bias)

// ---------------- helpers ----------------
__device__ __forceinline__ uint32_t smem_u32(const void* p) {
    uint32_t a; asm("{ .reg .u64 t; cvta.to.shared.u64 t, %1; cvt.u32.u64 %0, t; }" : "=r"(a) : "l"(p));
    return a;
}
__device__ __forceinline__ void ldm4(uint32_t* a, uint32_t addr) {
    asm volatile("ldmatrix.sync.aligned.m8n8.x4.shared.b16 {%0,%1,%2,%3}, [%4];"
        : "=r"(a[0]), "=r"(a[1]), "=r"(a[2]), "=r"(a[3]) : "r"(addr));
}
__device__ __forceinline__ void mma16816(float* d, const uint32_t* a, uint32_t b0, uint32_t b1,
                                         const float* c) {
    asm("mma.sync.aligned.m16n8k16.row.col.f32.f16.f16.f32 "
        "{%0,%1,%2,%3}, {%4,%5,%6,%7}, {%8,%9}, {%10,%11,%12,%13};"
        : "=f"(d[0]), "=f"(d[1]), "=f"(d[2]), "=f"(d[3])
        : "r"(a[0]), "r"(a[1]), "r"(a[2]), "r"(a[3]), "r"(b0), "r"(b1),
          "f"(c[0]), "f"(c[1]), "f"(c[2]), "f"(c[3]));
}
__device__ __forceinline__ uint32_t phh(float hi, float lo) {   // pack {lo(even k), hi(odd k)}
    uint32_t r; asm("cvt.rn.f16x2.f32 %0, %1, %2;" : "=r"(r) : "f"(hi), "f"(lo)); return r;
}
__device__ __forceinline__ uint32_t pack_h2(float a, float b) { // pack {a at lo, b at hi}
    uint32_t r; asm("cvt.rn.f16x2.f32 %0, %1, %2;" : "=r"(r) : "f"(b), "f"(a)); return r;
}
__device__ __forceinline__ uint32_t relu2(uint32_t v) {         // max.f16x2(v, 0)
    uint32_t r, z = 0u;
    asm("max.f16x2 %0, %1, %2;" : "=r"(r) : "r"(v), "r"(z));
    return r;
}
__device__ __forceinline__ float sigf(float v) { return 1.0f / (1.0f + __expf(-v)); }

// relu(f16x2) pack of previous-layer D into this layer's A fragments (K=80, 5 ktiles)
__device__ __forceinline__ void build_af(uint32_t (&af)[5][4], const float (&D)[9][4], uint32_t bc) {
    #pragma unroll
    for (int kt = 0; kt < 4; kt++) {
        af[kt][0] = relu2(phh(D[2*kt][1],   D[2*kt][0]));
        af[kt][1] = relu2(phh(D[2*kt][3],   D[2*kt][2]));
        af[kt][2] = relu2(phh(D[2*kt+1][1], D[2*kt+1][0]));
        af[kt][3] = relu2(phh(D[2*kt+1][3], D[2*kt+1][2]));
    }
    af[4][0] = relu2(phh(D[8][1], D[8][0]));
    af[4][1] = relu2(phh(D[8][3], D[8][2]));
    af[4][2] = bc;     // A[.][72]=1.0h (bias feed), rest 0
    af[4][3] = bc;
}

// ---------------- weight fragment prep ----------------
__device__ float wv(int sec, int hl, int k, int n,
    const float* Rsw, const float* Rsb, const float* Rhw, const float* Rhb,
    const float* Rew, const float* Reb,
    const float* Psw, const float* Psb, const float* Phw, const float* Phb,
    const float* Pew, const float* Peb) {
    if (sec == 0) {                       // L1: K=16 (k<10 feats, k=10 bias)
        if (n < 35) { if (k < 10) return Rsw[n*10 + k]; if (k == 10) return Rsb[n]; }
        else if (n >= 36 && n < 71) {
            int m = n - 36;
            if (k < 10) return Psw[m*10 + (9 - k)];   // P input reversal folded
            if (k == 10) return Psb[m];
        }
        return 0.f;
    }
    if (sec == 1) {                       // hidden hl: K=80, bias k=72
        if (n < 35) { if (k < 35) return Rhw[hl*1225 + n*35 + k]; if (k == 72) return Rhb[hl*35 + n]; }
        else if (n >= 36 && n < 71) {
            int m = n - 36;
            if (k >= 36 && k < 71) return Phw[hl*1225 + m*35 + (k - 36)];
            if (k == 72) return Phb[hl*35 + m];
        }
        return 0.f;
    }
    // end: N=16 (R j at n=0..4, P j at n=8..12), K=80, bias k=72
    if (n < 5) { if (k < 35) return Rew[n*35 + k]; if (k == 72) return Reb[n]; }
    else if (n >= 8 && n < 13) {
        int m = n - 8;
        if (k >= 36 && k < 71) return Pew[m*35 + (k - 36)];
        if (k == 72) return Peb[m];
    }
    return 0.f;
}

__device__ int kth_bit(int mask, int rank) {
    for (int k = 0; k < 5; k++)
        if (mask & (1 << k)) { if (rank == 0) return k; rank--; }
    return 0;
}

__global__ void k_prep(
    const float* Rsw, const float* Rsb, const float* Rhw, const float* Rhb,
    const float* Rew, const float* Reb,
    const float* Psw, const float* Psb, const float* Phw, const float* Phb,
    const float* Pew, const float* Peb) {
    const int hb[10] = {0, 4, 8, 12, 16, 21, 24, 27, 30};  // hidden per-layer nt bases
    int i0 = blockIdx.x * blockDim.x + threadIdx.x;
    for (int i = i0; i < NFRAG * 32; i += blockDim.x * gridDim.x) {
        int f = i >> 5, l = i & 31;
        int sec, hl = 0, kt = 0, nt;
        if (f < 9)        { sec = 0; nt = f; }
        else if (f < 108) {
            int g = f - 9; sec = 1; hl = g / 33; int w = g % 33;
            nt = 8;
            for (int q = 0; q < 8; q++) if (w < hb[q + 1]) { nt = q; break; }
            int mask = (nt < 4) ? HM_LO : (nt == 4) ? HM_MID : HM_HI;
            kt = kth_bit(mask, w - hb[nt]);
        } else {
            int g = f - 108; sec = 2;
            if (g < 4) { nt = 0; kt = kth_bit(HM_LO, g); }
            else       { nt = 1; kt = kth_bit(HM_HI, g - 4); }
        }
        int n  = nt * 8 + (l >> 2);
        int k0 = kt * 16 + 2 * (l & 3);
        float w0 = wv(sec, hl, k0,     n, Rsw,Rsb,Rhw,Rhb,Rew,Reb,Psw,Psb,Phw,Phb,Pew,Peb);
        float w1 = wv(sec, hl, k0 + 1, n, Rsw,Rsb,Rhw,Rhb,Rew,Reb,Psw,Psb,Phw,Phb,Pew,Peb);
        float w8 = wv(sec, hl, k0 + 8, n, Rsw,Rsb,Rhw,Rhb,Rew,Reb,Psw,Psb,Phw,Phb,Pew,Peb);
        float w9 = wv(sec, hl, k0 + 9, n, Rsw,Rsb,Rhw,Rhb,Rew,Reb,Psw,Psb,Phw,Phb,Pew,Peb);
        uint2 o;
        o.x = pack_h2(w0, w1);
        o.y = pack_h2(w8, w9);
        g_wfrag[i] = o;
    }
}

__global__ void k_noop() {}

// ---------------- edge kernel (HMMA m16n8k16, T=2, direct-fragment scatter) ----------------
#define WF_BYTES (NFRAG * 32 * 8)            // 29440
#define XT_OFF   WF_BYTES                    // 4 warps x 1024B (32 edges x 16 half)
#define SMEMB    (WF_BYTES + 4 * 1024)       // 33536

__global__ void __launch_bounds__(128, 4)
k_edges(const float* __restrict__ score, const int* __restrict__ edge_idx,
        const float* __restrict__ outcome, int E, int npairs) {
    extern __shared__ char sm[];
    const int tid = threadIdx.x;
    const int wid = tid >> 5, lane = tid & 31;

    // stage B fragments into smem
    {
        const uint4* src = (const uint4*)g_wfrag;
        uint4* dst = (uint4*)sm;
        for (int i = tid; i < WF_BYTES / 16; i += 128) dst[i] = src[i];
    }
    __syncthreads();

    const uint2* wfl = ((const uint2*)sm) + lane;
    __half* xt = (__half*)(sm + XT_OFF + wid * 1024);
    const uint32_t xt_ldm0 = smem_u32(xt) + (lane & 15) * 32 + (lane >> 4) * 16;
    const uint32_t xt_ldm1 = xt_ldm0 + 512;

    const int r = lane & 15, hh = lane >> 4;
    const int r0 = lane >> 2, c0 = 2 * (lane & 3);
    const uint32_t bc = ((lane & 3) == 0) ? 0x00003C00u : 0u;
    const int gw = blockIdx.x * 4 + wid, gstride = gridDim.x * 4;

    for (int p = gw; p < npairs; p += gstride) {
        const int ebase = p * 32 + r;
        uint32_t pb = 0;   // bit tt: pos of edge (p*32 + tt*16 + r)
        // ---- gather: per lane, its row in both tiles; 5 features each (hh half) ----
        #pragma unroll
        for (int tt = 0; tt < 2; tt++) {
            const int e = ebase + tt * 16;
            const int ec = (e < E) ? e : E - 1;
            const bool pos = outcome[ec] > 0.f;
            pb |= (pos ? 1u : 0u) << tt;
            const int* ep = edge_idx + (long long)ec * 10;
            __half* row = xt + (tt * 16 + r) * 16;
            #pragma unroll
            for (int j = 0; j < 5; j++) {
                const int fk = 5 * hh + j;
                const int ii = pos ? fk : 9 - fk;
                row[fk] = __float2half_rn(__ldg(score + __ldg(ep + ii)));
            }
            if (hh == 0) { row[10] = __float2half_rn(1.f); row[11] = __float2half_rn(0.f); }
            else         { *(uint32_t*)(row + 12) = 0u; *(uint32_t*)(row + 14) = 0u; }
        }
        __syncwarp();

        // ---- layer 1: shared B, two A tiles (dense in n) ----
        float D0[9][4], D1[9][4];
        {
            uint32_t a0[4], a1[4];
            ldm4(a0, xt_ldm0);
            ldm4(a1, xt_ldm1);
            const float z[4] = {0.f, 0.f, 0.f, 0.f};
            #pragma unroll
            for (int nt = 0; nt < 9; nt++) {
                uint2 b = wfl[nt * 32];
                mma16816(D0[nt], a0, b.x, b.y, z);
                mma16816(D1[nt], a1, b.x, b.y, z);
            }
        }

        // ---- 3 hidden layers + end layer: packed fragment index (constant-folded) ----
        int fi = 9;
        #pragma unroll
        for (int hl = 0; hl < 3; hl++) {
            uint32_t af0[5][4], af1[5][4];
            build_af(af0, D0, bc);
            build_af(af1, D1, bc);
            #pragma unroll
            for (int nt = 0; nt < 9; nt++) {
                const int mask = (nt < 4) ? HM_LO : (nt == 4) ? HM_MID : HM_HI;
                float a0[4] = {0.f,0.f,0.f,0.f}, a1[4] = {0.f,0.f,0.f,0.f};
                #pragma unroll
                for (int kt = 0; kt < 5; kt++) {
                    if (mask & (1 << kt)) {
                        uint2 b = wfl[fi * 32]; fi++;
                        mma16816(a0, af0[kt], b.x, b.y, a0);
                        mma16816(a1, af1[kt], b.x, b.y, a1);
                    }
                }
                #pragma unroll
                for (int q = 0; q < 4; q++) { D0[nt][q] = a0[q]; D1[nt][q] = a1[q]; }
            }
        }

        float de0[2][4], de1[2][4];
        {
            uint32_t af0[5][4], af1[5][4];
            build_af(af0, D0, bc);
            build_af(af1, D1, bc);
            #pragma unroll
            for (int nt = 0; nt < 2; nt++) {
                const int mask = (nt == 0) ? HM_LO : HM_HI;
                float a0[4] = {0.f,0.f,0.f,0.f}, a1[4] = {0.f,0.f,0.f,0.f};
                #pragma unroll
                for (int kt = 0; kt < 5; kt++) {
                    if (mask & (1 << kt)) {
                        uint2 b = wfl[fi * 32]; fi++;
                        mma16816(a0, af0[kt], b.x, b.y, a0);
                        mma16816(a1, af1[kt], b.x, b.y, a1);
                    }
                }
                #pragma unroll
                for (int q = 0; q < 4; q++) { de0[nt][q] = a0[q]; de1[nt][q] = a1[q]; }
            }
        }

        // ---- direct-fragment scatter ----
        // Lane holds, for each tile tt: rows r0 (q 0,1) and r0+8 (q 2,3); nt=0 -> R cols c0,c0+1;
        // nt=1 -> P cols c0,c0+1. Slot j of R goes to id[oR+j], of P to id[(5-oR)+j] with
        // oR = pos ? 0 : 5. pos for row m comes via shuffle from lane m (gather assignment).
        const uint32_t pbA = __shfl_sync(~0u, pb, r0);        // rows r0
        const uint32_t pbB = __shfl_sync(~0u, pb, r0 + 8);    // rows r0+8
        if (c0 < 5) {
            const bool two = (c0 + 1 < 5);   // c0 in {0,2}: 2 slots; c0==4: 1 slot
            #pragma unroll
            for (int tt = 0; tt < 2; tt++) {
                #pragma unroll
                for (int half = 0; half < 2; half++) {
                    const int m = r0 + 8 * half;
                    const int e = p * 32 + tt * 16 + m;
                    if (e < E) {
                        const uint32_t pm = ((half ? pbB : pbA) >> tt) & 1u;
                        const int oR = pm ? 0 : 5;
                        const long long eb = (long long)e * 10;
                        const float* dR = half ? ((tt ? de1 : de0)[0] + 2) : (tt ? de1 : de0)[0];
                        const float* dP = half ? ((tt ? de1 : de0)[1] + 2) : (tt ? de1 : de0)[1];
                        atomicAdd(&g_nd[__ldg(edge_idx + eb + oR + c0)],
                                  make_float2( sigf(dR[0]), 1.f));
                        atomicAdd(&g_nd[__ldg(edge_idx + eb + (5 - oR) + c0)],
                                  make_float2(-sigf(dP[0]), 1.f));
                        if (two) {
                            atomicAdd(&g_nd[__ldg(edge_idx + eb + oR + c0 + 1)],
                                      make_float2( sigf(dR[1]), 1.f));
                            atomicAdd(&g_nd[__ldg(edge_idx + eb + (5 - oR) + c0 + 1)],
                                      make_float2(-sigf(dP[1]), 1.f));
                        }
                    }
                }
            }
        }
        __syncwarp();
    }
}

// ---------------- epilogue ----------------
__global__ void k_init(int n) {
    int i = blockIdx.x * blockDim.x + threadIdx.x;
    if (i < n) g_nd[i] = make_float2(0.f, 0.f);
    if (i == 0) {
        g_degmax = 0.f;
        g_sum_s = 0.f; g_sum_a = 0.f; g_sum_ss = 0.f; g_sum_aa = 0.f; g_sum_sa = 0.f;
    }
}

__global__ void k_reduce(const float* __restrict__ score, int n) {
    __shared__ float w0[8], w1[8], w2[8], w3[8], w4[8], wm[8];
    int i = blockIdx.x * 256 + threadIdx.x;
    float s = 0.f, a = 0.f, d = 0.f;
    if (i < n) { s = score[i]; float2 nd = g_nd[i]; a = nd.x; d = nd.y; }
    float ss = s*s, aa = a*a, sa = s*a;
    #pragma unroll
    for (int o = 16; o > 0; o >>= 1) {
        s += __shfl_down_sync(~0u, s, o);  a += __shfl_down_sync(~0u, a, o);
        ss += __shfl_down_sync(~0u, ss, o); aa += __shfl_down_sync(~0u, aa, o);
        sa += __shfl_down_sync(~0u, sa, o); d = fmaxf(d, __shfl_down_sync(~0u, d, o));
    }
    int lane = threadIdx.x & 31, wd = threadIdx.x >> 5;
    if (lane == 0) { w0[wd]=s; w1[wd]=a; w2[wd]=ss; w3[wd]=aa; w4[wd]=sa; wm[wd]=d; }
    __syncthreads();
    if (wd == 0) {
        s  = (lane < 8) ? w0[lane] : 0.f;  a  = (lane < 8) ? w1[lane] : 0.f;
        ss = (lane < 8) ? w2[lane] : 0.f;  aa = (lane < 8) ? w3[lane] : 0.f;
        sa = (lane < 8) ? w4[lane] : 0.f;  d  = (lane < 8) ? wm[lane] : 0.f;
        #pragma unroll
        for (int o = 4; o > 0; o >>= 1) {
            s += __shfl_down_sync(~0u, s, o);  a += __shfl_down_sync(~0u, a, o);
            ss += __shfl_down_sync(~0u, ss, o); aa += __shfl_down_sync(~0u, aa, o);
            sa += __shfl_down_sync(~0u, sa, o); d = fmaxf(d, __shfl_down_sync(~0u, d, o));
        }
        if (lane == 0) {
            atomicAdd(&g_sum_s, s);  atomicAdd(&g_sum_a, a);
            atomicAdd(&g_sum_ss, ss); atomicAdd(&g_sum_aa, aa);
            atomicAdd(&g_sum_sa, sa);
            atomicMax((int*)&g_degmax, __float_as_int(d));   // values >= 0
        }
    }
}

__global__ void k_final(const float* __restrict__ score, float* __restrict__ out, int n) {
    int i = blockIdx.x * blockDim.x + threadIdx.x;
    if (i < n) {
        float scale = 2.0f / g_degmax;
        float mean  = (g_sum_s + scale * g_sum_a) / (float)n;
        float sumsq = g_sum_ss + 2.f * scale * g_sum_sa + scale * scale * g_sum_aa;
        float norm  = sqrtf(fmaxf(sumsq - (float)n * mean * mean, 1e-30f));
        float t = score[i] + scale * g_nd[i].x;
        out[i] = (t - mean) / norm;
    }
}

extern "C" void kernel_launch(void* const* d_in, const int* in_sizes, int n_in,
                              void* d_out, int out_size) {
    const float* score    = (const float*)d_in[0];
    const int*   edge_idx = (const int*)  d_in[1];
    const float* outcome  = (const float*)d_in[2];
    const float* Rsw = (const float*)d_in[3];
    const float* Rsb = (const float*)d_in[4];
    const float* Rhw = (const float*)d_in[5];
    const float* Rhb = (const float*)d_in[6];
    const float* Rew = (const float*)d_in[7];
    const float* Reb = (const float*)d_in[8];
    const float* Psw = (const float*)d_in[9];
    const float* Psb = (const float*)d_in[10];
    const float* Phw = (const float*)d_in[11];
    const float* Phb = (const float*)d_in[12];
    const float* Pew = (const float*)d_in[13];
    const float* Peb = (const float*)d_in[14];

    const int N = in_sizes[0];
    const int E = in_sizes[2];
    const int npairs = (E + 31) / 32;

    cudaFuncSetAttribute(k_edges, cudaFuncAttributeMaxDynamicSharedMemorySize, SMEMB);

    const int nb = (N + 255) / 256;
    k_init<<<nb, 256>>>(N);                                   // 0
    k_prep<<<15, 256>>>(Rsw, Rsb, Rhw, Rhb, Rew, Reb,
                        Psw, Psb, Phw, Phb, Pew, Peb);        // 1
    k_noop<<<1, 32>>>();                                      // 2
    k_edges<<<592, 128, SMEMB>>>(score, edge_idx, outcome, E, npairs);  // 3 (ncu slot)
    k_reduce<<<nb, 256>>>(score, N);                          // 4
    k_final<<<nb, 256>>>(score, (float*)d_out, N);            // 5
}

// round 10
// speedup vs baseline: 1.0856x; 1.0856x over previous
#include <cuda_runtime.h>
#include <cuda_fp16.h>
#include <math.h>
#include <stdint.h>

#define NN 100000

// ---------------- scratch ----------------
__device__ __align__(8) float2 g_nd[NN];     // (agg, deg) fused
__device__ float g_degmax;
__device__ float g_sum_s, g_sum_a, g_sum_ss, g_sum_aa, g_sum_sa;

// Compacted per-lane B fragments (only nonzero ones, 115 total):
//   L1: f 0..8 (nt, kt=0)
//   Hidden hl: f 9+33*hl + packed(nt, kt in mask, kt-ascending)
//   End: f 108..114 (nt0: 4 frags mask HM_LO, nt1: 3 frags mask HM_HI)
// frag f, lane l: .x = pack(B[k0][n], B[k0+1][n]), .y = pack(B[k0+8][n], B[k0+9][n])
//   with n = nt*8 + l/4, k0 = kt*16 + 2*(l%4)   (B[k][n] = W[n][k])
#define NFRAG 115
__device__ __align__(16) uint2 g_wfrag[NFRAG * 32];

#define HM_LO  0b10111    // hidden, nt 0..3  (R block + bias)
#define HM_MID 0b11111    // hidden, nt 4
#define HM_HI  0b11100    // hidden, nt 5..8  (P block + bias)

// ---------------- helpers ----------------
__device__ __forceinline__ uint32_t smem_u32(const void* p) {
    uint32_t a; asm("{ .reg .u64 t; cvta.to.shared.u64 t, %1; cvt.u32.u64 %0, t; }" : "=r"(a) : "l"(p));
    return a;
}
__device__ __forceinline__ void ldm4(uint32_t* a, uint32_t addr) {
    asm volatile("ldmatrix.sync.aligned.m8n8.x4.shared.b16 {%0,%1,%2,%3}, [%4];"
        : "=r"(a[0]), "=r"(a[1]), "=r"(a[2]), "=r"(a[3]) : "r"(addr));
}
__device__ __forceinline__ void mma16816(float* d, const uint32_t* a, uint32_t b0, uint32_t b1,
                                         const float* c) {
    asm("mma.sync.aligned.m16n8k16.row.col.f32.f16.f16.f32 "
        "{%0,%1,%2,%3}, {%4,%5,%6,%7}, {%8,%9}, {%10,%11,%12,%13};"
        : "=f"(d[0]), "=f"(d[1]), "=f"(d[2]), "=f"(d[3])
        : "r"(a[0]), "r"(a[1]), "r"(a[2]), "r"(a[3]), "r"(b0), "r"(b1),
          "f"(c[0]), "f"(c[1]), "f"(c[2]), "f"(c[3]));
}
__device__ __forceinline__ uint32_t phh(float hi, float lo) {
    uint32_t r; asm("cvt.rn.f16x2.f32 %0, %1, %2;" : "=r"(r) : "f"(hi), "f"(lo)); return r;
}
__device__ __forceinline__ uint32_t pack_h2(float a, float b) {
    uint32_t r; asm("cvt.rn.f16x2.f32 %0, %1, %2;" : "=r"(r) : "f"(b), "f"(a)); return r;
}
__device__ __forceinline__ uint32_t relu2(uint32_t v) {
    uint32_t r, z = 0u;
    asm("max.f16x2 %0, %1, %2;" : "=r"(r) : "r"(v), "r"(z));
    return r;
}
__device__ __forceinline__ float sigf(float v) { return 1.0f / (1.0f + __expf(-v)); }

__device__ __forceinline__ void build_af(uint32_t (&af)[5][4], const float (&D)[9][4], uint32_t bc) {
    #pragma unroll
    for (int kt = 0; kt < 4; kt++) {
        af[kt][0] = relu2(phh(D[2*kt][1],   D[2*kt][0]));
        af[kt][1] = relu2(phh(D[2*kt][3],   D[2*kt][2]));
        af[kt][2] = relu2(phh(D[2*kt+1][1], D[2*kt+1][0]));
        af[kt][3] = relu2(phh(D[2*kt+1][3], D[2*kt+1][2]));
    }
    af[4][0] = relu2(phh(D[8][1], D[8][0]));
    af[4][1] = relu2(phh(D[8][3], D[8][2]));
    af[4][2] = bc;
    af[4][3] = bc;
}

// ---------------- weight fragment prep ----------------
__device__ float wv(int sec, int hl, int k, int n,
    const float* Rsw, const float* Rsb, const float* Rhw, const float* Rhb,
    const float* Rew, const float* Reb,
    const float* Psw, const float* Psb, const float* Phw, const float* Phb,
    const float* Pew, const float* Peb) {
    if (sec == 0) {
        if (n < 35) { if (k < 10) return Rsw[n*10 + k]; if (k == 10) return Rsb[n]; }
        else if (n >= 36 && n < 71) {
            int m = n - 36;
            if (k < 10) return Psw[m*10 + (9 - k)];
            if (k == 10) return Psb[m];
        }
        return 0.f;
    }
    if (sec == 1) {
        if (n < 35) { if (k < 35) return Rhw[hl*1225 + n*35 + k]; if (k == 72) return Rhb[hl*35 + n]; }
        else if (n >= 36 && n < 71) {
            int m = n - 36;
            if (k >= 36 && k < 71) return Phw[hl*1225 + m*35 + (k - 36)];
            if (k == 72) return Phb[hl*35 + m];
        }
        return 0.f;
    }
    if (n < 5) { if (k < 35) return Rew[n*35 + k]; if (k == 72) return Reb[n]; }
    else if (n >= 8 && n < 13) {
        int m = n - 8;
        if (k >= 36 && k < 71) return Pew[m*35 + (k - 36)];
        if (k == 72) return Peb[m];
    }
    return 0.f;
}

__device__ int kth_bit(int mask, int rank) {
    for (int k = 0; k < 5; k++)
        if (mask & (1 << k)) { if (rank == 0) return k; rank--; }
    return 0;
}

__global__ void k_prep(
    const float* Rsw, const float* Rsb, const float* Rhw, const float* Rhb,
    const float* Rew, const float* Reb,
    const float* Psw, const float* Psb, const float* Phw, const float* Phb,
    const float* Pew, const float* Peb) {
    const int hb[10] = {0, 4, 8, 12, 16, 21, 24, 27, 30};
    int i0 = blockIdx.x * blockDim.x + threadIdx.x;
    for (int i = i0; i < NFRAG * 32; i += blockDim.x * gridDim.x) {
        int f = i >> 5, l = i & 31;
        int sec, hl = 0, kt = 0, nt;
        if (f < 9)        { sec = 0; nt = f; }
        else if (f < 108) {
            int g = f - 9; sec = 1; hl = g / 33; int w = g % 33;
            nt = 8;
            for (int q = 0; q < 8; q++) if (w < hb[q + 1]) { nt = q; break; }
            int mask = (nt < 4) ? HM_LO : (nt == 4) ? HM_MID : HM_HI;
            kt = kth_bit(mask, w - hb[nt]);
        } else {
            int g = f - 108; sec = 2;
            if (g < 4) { nt = 0; kt = kth_bit(HM_LO, g); }
            else       { nt = 1; kt = kth_bit(HM_HI, g - 4); }
        }
        int n  = nt * 8 + (l >> 2);
        int k0 = kt * 16 + 2 * (l & 3);
        float w0 = wv(sec, hl, k0,     n, Rsw,Rsb,Rhw,Rhb,Rew,Reb,Psw,Psb,Phw,Phb,Pew,Peb);
        float w1 = wv(sec, hl, k0 + 1, n, Rsw,Rsb,Rhw,Rhb,Rew,Reb,Psw,Psb,Phw,Phb,Pew,Peb);
        float w8 = wv(sec, hl, k0 + 8, n, Rsw,Rsb,Rhw,Rhb,Rew,Reb,Psw,Psb,Phw,Phb,Pew,Peb);
        float w9 = wv(sec, hl, k0 + 9, n, Rsw,Rsb,Rhw,Rhb,Rew,Reb,Psw,Psb,Phw,Phb,Pew,Peb);
        uint2 o;
        o.x = pack_h2(w0, w1);
        o.y = pack_h2(w8, w9);
        g_wfrag[i] = o;
    }
}

__global__ void k_noop() {}

// ---------------- edge kernel (HMMA, T=2, idx staging + gather pipelining) ----------------
#define WF_BYTES (NFRAG * 32 * 8)            // 29440
#define XT_OFF   WF_BYTES                    // 4 warps x 1024B
#define IB_OFF   (WF_BYTES + 4 * 1024)       // 4 warps x 2 x 1280B idx double buffer
#define SMEMB    (IB_OFF + 4 * 2560)         // 43776

// coalesced load of one pair-tile's edge indices (320 ints) into smem
__device__ __forceinline__ void load_idx(int* dst, const int* __restrict__ edge_idx,
                                         int p, int lane, int E) {
    const long long base = (long long)p * 320;
    if ((long long)(p + 1) * 32 <= (long long)E) {
        const int4* src = (const int4*)(edge_idx + base);
        int4* d4 = (int4*)dst;
        d4[lane] = __ldg(src + lane);
        d4[lane + 32] = __ldg(src + lane + 32);
        if (lane < 16) d4[lane + 64] = __ldg(src + lane + 64);
    } else {
        const long long mx = (long long)E * 10 - 1;
        for (int i = lane; i < 320; i += 32) {
            long long g = base + i;
            dst[i] = edge_idx[g <= mx ? g : mx];
        }
    }
}

// prefetch scores + outcome for pair p using staged idx
__device__ __forceinline__ void prefetch_x(const int* __restrict__ ib,
        const float* __restrict__ score, const float* __restrict__ outcome,
        int p, int E, int r, int hh, float (&xs)[2][5], uint32_t& pb) {
    pb = 0;
    #pragma unroll
    for (int tt = 0; tt < 2; tt++) {
        const int e = p * 32 + tt * 16 + r;
        const int ec = (e < E) ? e : E - 1;
        const bool pos = outcome[ec] > 0.f;
        pb |= (pos ? 1u : 0u) << tt;
        const int* row = ib + (tt * 16 + r) * 10;
        #pragma unroll
        for (int j = 0; j < 5; j++) {
            const int fk = 5 * hh + j;
            const int ii = pos ? fk : 9 - fk;
            xs[tt][j] = __ldg(score + row[ii]);
        }
    }
}

__global__ void __launch_bounds__(128, 3)
k_edges(const float* __restrict__ score, const int* __restrict__ edge_idx,
        const float* __restrict__ outcome, int E, int npairs) {
    extern __shared__ char sm[];
    const int tid = threadIdx.x;
    const int wid = tid >> 5, lane = tid & 31;

    {
        const uint4* src = (const uint4*)g_wfrag;
        uint4* dst = (uint4*)sm;
        for (int i = tid; i < WF_BYTES / 16; i += 128) dst[i] = src[i];
    }
    __syncthreads();

    const uint2* wfl = ((const uint2*)sm) + lane;
    __half* xt = (__half*)(sm + XT_OFF + wid * 1024);
    int* ibb = (int*)(sm + IB_OFF + wid * 2560);
    const uint32_t xt_ldm0 = smem_u32(xt) + (lane & 15) * 32 + (lane >> 4) * 16;
    const uint32_t xt_ldm1 = xt_ldm0 + 512;

    const int r = lane & 15, hh = lane >> 4;
    const int r0 = lane >> 2, c0 = 2 * (lane & 3);
    const uint32_t bc = ((lane & 3) == 0) ? 0x00003C00u : 0u;
    const int gw = blockIdx.x * 4 + wid, gstride = gridDim.x * 4;

    if (gw >= npairs) return;

    // prologue: stage idx + prefetch scores for first pair
    int buf = 0;
    float xs[2][5];
    uint32_t pb;
    load_idx(ibb, edge_idx, gw, lane, E);
    __syncwarp();
    prefetch_x(ibb, score, outcome, gw, E, r, hh, xs, pb);

    for (int p = gw; p < npairs; p += gstride) {
        const int pn = p + gstride;
        int* ibC = ibb + buf * 320;
        int* ibN = ibb + (buf ^ 1) * 320;

        // ---- store xt from prefetched regs ----
        #pragma unroll
        for (int tt = 0; tt < 2; tt++) {
            __half* row = xt + (tt * 16 + r) * 16;
            #pragma unroll
            for (int j = 0; j < 5; j++) row[5 * hh + j] = __float2half_rn(xs[tt][j]);
            if (hh == 0) { row[10] = __float2half_rn(1.f); row[11] = __float2half_rn(0.f); }
            else         { *(uint32_t*)(row + 12) = 0u; *(uint32_t*)(row + 14) = 0u; }
        }
        __syncwarp();

        // ---- kick off next pair's idx staging (overlaps with layer 1) ----
        if (pn < npairs) load_idx(ibN, edge_idx, pn, lane, E);

        // ---- layer 1 ----
        float D0[9][4], D1[9][4];
        {
            uint32_t a0[4], a1[4];
            ldm4(a0, xt_ldm0);
            ldm4(a1, xt_ldm1);
            const float z[4] = {0.f, 0.f, 0.f, 0.f};
            #pragma unroll
            for (int nt = 0; nt < 9; nt++) {
                uint2 b = wfl[nt * 32];
                mma16816(D0[nt], a0, b.x, b.y, z);
                mma16816(D1[nt], a1, b.x, b.y, z);
            }
        }
        __syncwarp();   // ibN visible to all lanes

        // ---- prefetch next pair's scores (latency hidden behind layers 2..end) ----
        float xsN[2][5];
        uint32_t pbN = 0;
        if (pn < npairs) prefetch_x(ibN, score, outcome, pn, E, r, hh, xsN, pbN);

        // ---- hidden layers ----
        int fi = 9;
        #pragma unroll
        for (int hl = 0; hl < 3; hl++) {
            uint32_t af0[5][4], af1[5][4];
            build_af(af0, D0, bc);
            build_af(af1, D1, bc);
            #pragma unroll
            for (int nt = 0; nt < 9; nt++) {
                const int mask = (nt < 4) ? HM_LO : (nt == 4) ? HM_MID : HM_HI;
                float a0[4] = {0.f,0.f,0.f,0.f}, a1[4] = {0.f,0.f,0.f,0.f};
                #pragma unroll
                for (int kt = 0; kt < 5; kt++) {
                    if (mask & (1 << kt)) {
                        uint2 b = wfl[fi * 32]; fi++;
                        mma16816(a0, af0[kt], b.x, b.y, a0);
                        mma16816(a1, af1[kt], b.x, b.y, a1);
                    }
                }
                #pragma unroll
                for (int q = 0; q < 4; q++) { D0[nt][q] = a0[q]; D1[nt][q] = a1[q]; }
            }
        }

        // ---- end layer ----
        float de0[2][4], de1[2][4];
        {
            uint32_t af0[5][4], af1[5][4];
            build_af(af0, D0, bc);
            build_af(af1, D1, bc);
            #pragma unroll
            for (int nt = 0; nt < 2; nt++) {
                const int mask = (nt == 0) ? HM_LO : HM_HI;
                float a0[4] = {0.f,0.f,0.f,0.f}, a1[4] = {0.f,0.f,0.f,0.f};
                #pragma unroll
                for (int kt = 0; kt < 5; kt++) {
                    if (mask & (1 << kt)) {
                        uint2 b = wfl[fi * 32]; fi++;
                        mma16816(a0, af0[kt], b.x, b.y, a0);
                        mma16816(a1, af1[kt], b.x, b.y, a1);
                    }
                }
                #pragma unroll
                for (int q = 0; q < 4; q++) { de0[nt][q] = a0[q]; de1[nt][q] = a1[q]; }
            }
        }

        // ---- direct-fragment scatter (idx from staged smem) ----
        const uint32_t pbA = __shfl_sync(~0u, pb, r0);
        const uint32_t pbB = __shfl_sync(~0u, pb, r0 + 8);
        if (c0 < 5) {
            const bool two = (c0 + 1 < 5);
            #pragma unroll
            for (int tt = 0; tt < 2; tt++) {
                #pragma unroll
                for (int half = 0; half < 2; half++) {
                    const int m = r0 + 8 * half;
                    const int e = p * 32 + tt * 16 + m;
                    if (e < E) {
                        const uint32_t pm = ((half ? pbB : pbA) >> tt) & 1u;
                        const int oR = pm ? 0 : 5;
                        const int* row = ibC + (tt * 16 + m) * 10;
                        const float* dR = half ? ((tt ? de1 : de0)[0] + 2) : (tt ? de1 : de0)[0];
                        const float* dP = half ? ((tt ? de1 : de0)[1] + 2) : (tt ? de1 : de0)[1];
                        atomicAdd(&g_nd[row[oR + c0]],       make_float2( sigf(dR[0]), 1.f));
                        atomicAdd(&g_nd[row[(5 - oR) + c0]], make_float2(-sigf(dP[0]), 1.f));
                        if (two) {
                            atomicAdd(&g_nd[row[oR + c0 + 1]],       make_float2( sigf(dR[1]), 1.f));
                            atomicAdd(&g_nd[row[(5 - oR) + c0 + 1]], make_float2(-sigf(dP[1]), 1.f));
                        }
                    }
                }
            }
        }

        // rotate pipeline state
        #pragma unroll
        for (int tt = 0; tt < 2; tt++)
            #pragma unroll
            for (int j = 0; j < 5; j++) xs[tt][j] = xsN[tt][j];
        pb = pbN;
        buf ^= 1;
        __syncwarp();   // all lanes done with ibC before next iteration overwrites it
    }
}

// ---------------- epilogue ----------------
__global__ void k_init(int n) {
    int i = blockIdx.x * blockDim.x + threadIdx.x;
    if (i < n) g_nd[i] = make_float2(0.f, 0.f);
    if (i == 0) {
        g_degmax = 0.f;
        g_sum_s = 0.f; g_sum_a = 0.f; g_sum_ss = 0.f; g_sum_aa = 0.f; g_sum_sa = 0.f;
    }
}

__global__ void k_reduce(const float* __restrict__ score, int n) {
    __shared__ float w0[8], w1[8], w2[8], w3[8], w4[8], wm[8];
    int i = blockIdx.x * 256 + threadIdx.x;
    float s = 0.f, a = 0.f, d = 0.f;
    if (i < n) { s = score[i]; float2 nd = g_nd[i]; a = nd.x; d = nd.y; }
    float ss = s*s, aa = a*a, sa = s*a;
    #pragma unroll
    for (int o = 16; o > 0; o >>= 1) {
        s += __shfl_down_sync(~0u, s, o);  a += __shfl_down_sync(~0u, a, o);
        ss += __shfl_down_sync(~0u, ss, o); aa += __shfl_down_sync(~0u, aa, o);
        sa += __shfl_down_sync(~0u, sa, o); d = fmaxf(d, __shfl_down_sync(~0u, d, o));
    }
    int lane = threadIdx.x & 31, wd = threadIdx.x >> 5;
    if (lane == 0) { w0[wd]=s; w1[wd]=a; w2[wd]=ss; w3[wd]=aa; w4[wd]=sa; wm[wd]=d; }
    __syncthreads();
    if (wd == 0) {
        s  = (lane < 8) ? w0[lane] : 0.f;  a  = (lane < 8) ? w1[lane] : 0.f;
        ss = (lane < 8) ? w2[lane] : 0.f;  aa = (lane < 8) ? w3[lane] : 0.f;
        sa = (lane < 8) ? w4[lane] : 0.f;  d  = (lane < 8) ? wm[lane] : 0.f;
        #pragma unroll
        for (int o = 4; o > 0; o >>= 1) {
            s += __shfl_down_sync(~0u, s, o);  a += __shfl_down_sync(~0u, a, o);
            ss += __shfl_down_sync(~0u, ss, o); aa += __shfl_down_sync(~0u, aa, o);
            sa += __shfl_down_sync(~0u, sa, o); d = fmaxf(d, __shfl_down_sync(~0u, d, o));
        }
        if (lane == 0) {
            atomicAdd(&g_sum_s, s);  atomicAdd(&g_sum_a, a);
            atomicAdd(&g_sum_ss, ss); atomicAdd(&g_sum_aa, aa);
            atomicAdd(&g_sum_sa, sa);
            atomicMax((int*)&g_degmax, __float_as_int(d));
        }
    }
}

__global__ void k_final(const float* __restrict__ score, float* __restrict__ out, int n) {
    int i = blockIdx.x * blockDim.x + threadIdx.x;
    if (i < n) {
        float scale = 2.0f / g_degmax;
        float mean  = (g_sum_s + scale * g_sum_a) / (float)n;
        float sumsq = g_sum_ss + 2.f * scale * g_sum_sa + scale * scale * g_sum_aa;
        float norm  = sqrtf(fmaxf(sumsq - (float)n * mean * mean, 1e-30f));
        float t = score[i] + scale * g_nd[i].x;
        out[i] = (t - mean) / norm;
    }
}

extern "C" void kernel_launch(void* const* d_in, const int* in_sizes, int n_in,
                              void* d_out, int out_size) {
    const float* score    = (const float*)d_in[0];
    const int*   edge_idx = (const int*)  d_in[1];
    const float* outcome  = (const float*)d_in[2];
    const float* Rsw = (const float*)d_in[3];
    const float* Rsb = (const float*)d_in[4];
    const float* Rhw = (const float*)d_in[5];
    const float* Rhb = (const float*)d_in[6];
    const float* Rew = (const float*)d_in[7];
    const float* Reb = (const float*)d_in[8];
    const float* Psw = (const float*)d_in[9];
    const float* Psb = (const float*)d_in[10];
    const float* Phw = (const float*)d_in[11];
    const float* Phb = (const float*)d_in[12];
    const float* Pew = (const float*)d_in[13];
    const float* Peb = (const float*)d_in[14];

    const int N = in_sizes[0];
    const int E = in_sizes[2];
    const int npairs = (E + 31) / 32;

    cudaFuncSetAttribute(k_edges, cudaFuncAttributeMaxDynamicSharedMemorySize, SMEMB);

    const int nb = (N + 255) / 256;
    k_init<<<nb, 256>>>(N);                                   // 0
    k_prep<<<15, 256>>>(Rsw, Rsb, Rhw, Rhb, Rew, Reb,
                        Psw, Psb, Phw, Phb, Pew, Peb);        // 1
    k_noop<<<1, 32>>>();                                      // 2
    k_edges<<<456, 128, SMEMB>>>(score, edge_idx, outcome, E, npairs);  // 3 (ncu slot)
    k_reduce<<<nb, 256>>>(score, N);                          // 4
    k_final<<<nb, 256>>>(score, (float*)d_out, N);            // 5
}